// round 5
// baseline (speedup 1.0000x reference)
#include <cuda_runtime.h>
#include <cuda_bf16.h>
#include <cstdint>
#include <cstddef>

#define NA 120001
#define NB 260001
#define AF 133
#define BF 147
#define HD 256
#define MAXNB 6
#define NMOL 6000
#define APM 20

#define BMT 128           // M rows per CTA
#define BK  32            // K elements per chunk

#define KPAD_I 160
#define KPAD_H 256
#define KPAD_O 416

// SMEM per buffer (stride 80 B per 32-element bf16 row):
//   A_HI 128*80=10240, A_LO 10240, B_HI 256*80=20480, B_LO 20480  => 61440
#define OFF_A_HI 0
#define OFF_A_LO 10240
#define OFF_B_HI 20480
#define OFF_B_LO 40960
#define BUFSZ    61440
#define SMEM_TOTAL (2 * BUFSZ)   // 122880

typedef unsigned int u32;

// ---------------- scratch (device globals; no allocation allowed) ----------
__device__ float g_inp [(size_t)NB * HD];
__device__ float g_msgA[(size_t)NB * HD];
__device__ float g_msgB[(size_t)NB * HD];
__device__ float g_amsg[(size_t)NA * HD];
__device__ float g_hid [(size_t)NA * HD];

// prepacked transposed weights, bf16 hi/lo: [term][N=256][Kpad]
__device__ __nv_bfloat16 g_Bi[2][256 * KPAD_I];
__device__ __nv_bfloat16 g_Bh[2][256 * KPAD_H];
__device__ __nv_bfloat16 g_Bo[2][256 * KPAD_O];

// ---------------- helpers ---------------------------------------------------
__device__ __forceinline__ u32 smem_to_u32(const void* p) {
    u32 a;
    asm("{ .reg .u64 t; cvta.to.shared.u64 t, %1; cvt.u32.u64 %0, t; }"
        : "=r"(a) : "l"(p));
    return a;
}
__device__ __forceinline__ void ldsm_x4(u32& r0, u32& r1, u32& r2, u32& r3, u32 a) {
    asm volatile("ldmatrix.sync.aligned.m8n8.x4.shared.b16 {%0,%1,%2,%3}, [%4];"
                 : "=r"(r0), "=r"(r1), "=r"(r2), "=r"(r3) : "r"(a));
}
__device__ __forceinline__ void mma_bf16(float* c, const u32* a, const u32* b) {
    asm volatile(
        "mma.sync.aligned.m16n8k16.row.col.f32.bf16.bf16.f32 "
        "{%0,%1,%2,%3},{%4,%5,%6,%7},{%8,%9},{%0,%1,%2,%3};"
        : "+f"(c[0]), "+f"(c[1]), "+f"(c[2]), "+f"(c[3])
        : "r"(a[0]), "r"(a[1]), "r"(a[2]), "r"(a[3]), "r"(b[0]), "r"(b[1]));
}
__device__ __forceinline__ u32 pkh(__nv_bfloat16 a, __nv_bfloat16 b) {
    return (u32)__bfloat16_as_ushort(a) | ((u32)__bfloat16_as_ushort(b) << 16);
}
__device__ __forceinline__ void cp16(u32 dst, const void* src) {
    asm volatile("cp.async.cg.shared.global [%0], [%1], 16;"
                 :: "r"(dst), "l"(src));
}
#define CP_COMMIT() asm volatile("cp.async.commit_group;" ::: "memory")
#define CP_WAIT0()  asm volatile("cp.async.wait_group 0;"  ::: "memory")

// ---------------- weight prepack: transpose + hi/lo split + zero pad -------
__global__ void pack_w_kernel(const float* __restrict__ W, int sel)
{
    int KPAD = (sel == 0) ? KPAD_I : (sel == 1) ? KPAD_H : KPAD_O;
    __nv_bfloat16* imgHi = (sel == 0) ? g_Bi[0] : (sel == 1) ? g_Bh[0] : g_Bo[0];
    __nv_bfloat16* imgLo = (sel == 0) ? g_Bi[1] : (sel == 1) ? g_Bh[1] : g_Bo[1];
    int t = blockIdx.x * blockDim.x + threadIdx.x;
    if (t >= 256 * KPAD) return;
    int n = t / KPAD, kk = t % KPAD;
    int srck;
    if (sel == 0)      srck = (kk < BF) ? kk : -1;
    else if (sel == 1) srck = kk;
    else               srck = (kk < 160) ? (kk < AF ? kk : -1) : (AF + (kk - 160));
    float w = (srck >= 0) ? W[(size_t)srck * HD + n] : 0.f;
    __nv_bfloat16 hi = __float2bfloat16(w);
    __nv_bfloat16 lo = __float2bfloat16(w - __bfloat162float(hi));
    imgHi[(size_t)n * KPAD + kk] = hi;
    imgLo[(size_t)n * KPAD + kk] = lo;
}

// ---------------- unified mma.sync GEMM with cp.async double buffering -----
// MODE 0: g_inp = f_bonds @ W_i ; g_msgA = relu(g_inp)
// MODE 1: msgOut = relu(g_inp + (g_amsg[b2a] - msgIn[b2revb]) @ W_h)
// MODE 2: g_hid = relu([f_atoms | g_amsg] @ W_o + b_o)
template <int MODE>
__global__ void __launch_bounds__(256, 1) mma_gemm_kernel(
    const float* __restrict__ srcA,
    const int* __restrict__ b2a, const int* __restrict__ b2revb,
    const float* __restrict__ bo, int srcSel)
{
    constexpr int NCH   = (MODE == 0) ? 5 : (MODE == 1) ? 8 : 13;
    constexpr int KPAD  = (MODE == 0) ? KPAD_I : (MODE == 1) ? KPAD_H : KPAD_O;
    constexpr int Mrows = (MODE == 2) ? NA : NB;
    constexpr int KV    = (MODE == 0) ? BF : AF;

    const float* __restrict__ msgIn  = (srcSel == 0) ? g_msgA : g_msgB;
    float*       __restrict__ msgOut = (srcSel == 0) ? g_msgB : g_msgA;
    const __nv_bfloat16* imgHi =
        (MODE == 0) ? g_Bi[0] : (MODE == 1) ? g_Bh[0] : g_Bo[0];
    const __nv_bfloat16* imgLo =
        (MODE == 0) ? g_Bi[1] : (MODE == 1) ? g_Bh[1] : g_Bo[1];

    extern __shared__ char smem[];
    const u32 sbase = smem_to_u32(smem);

    const int tid  = threadIdx.x;
    const int lane = tid & 31;
    const int wid  = tid >> 5;
    const int wm   = wid >> 2;        // 0..1  (M: 64 rows each)
    const int wn   = wid & 3;         // 0..3  (N: 64 cols each)
    const int bm   = blockIdx.x * BMT;

    // A-loader coords: 2 threads per row, 16 cols each
    const int arow = tid >> 1;        // 0..127
    const int half = tid & 1;         // col group: half*16
    const int agr  = bm + arow;
    const float* p1 = nullptr;
    const float* p2 = nullptr;
    if (MODE == 1 && agr < NB) {
        p1 = g_amsg + (size_t)__ldg(b2a + agr)    * HD;
        p2 = msgIn  + (size_t)__ldg(b2revb + agr) * HD;
    }

    // ldmatrix lane addressing
    const int alrow = lane & 15;
    const int alk   = (lane & 16) ? 8 : 0;
    const int blrow = (lane & 7) + ((lane & 16) ? 8 : 0);
    const int blk   = (lane & 8)  ? 8 : 0;

    float acc[4][8][4];
#pragma unroll
    for (int i = 0; i < 4; i++)
#pragma unroll
        for (int j = 0; j < 8; j++)
#pragma unroll
            for (int q = 0; q < 4; q++) acc[i][j][q] = 0.f;

    float v[16];

    // ---- helpers as lambdas ----
    auto issue_B = [&](int ch, u32 bufB) {
#pragma unroll
        for (int i = 0; i < 4; i++) {
            int idx = tid + 256 * i;
            int n = idx >> 2, seg = idx & 3;
            cp16(bufB + OFF_B_HI + n * 80 + seg * 16,
                 imgHi + (size_t)n * KPAD + ch * BK + seg * 8);
            cp16(bufB + OFF_B_LO + n * 80 + seg * 16,
                 imgLo + (size_t)n * KPAD + ch * BK + seg * 8);
        }
        CP_COMMIT();
    };
    auto load_A = [&](int ch) {
        const bool vec = (MODE == 1) || (MODE == 2 && ch >= 5);
        if (vec) {
            if (agr < Mrows) {
                if (MODE == 1) {
                    int off = ch * BK + half * 16;
#pragma unroll
                    for (int q = 0; q < 4; q++) {
                        float4 a = *(const float4*)(p1 + off + q * 4);
                        float4 b = *(const float4*)(p2 + off + q * 4);
                        v[q * 4 + 0] = a.x - b.x; v[q * 4 + 1] = a.y - b.y;
                        v[q * 4 + 2] = a.z - b.z; v[q * 4 + 3] = a.w - b.w;
                    }
                } else {
                    int off = (ch - 5) * BK + half * 16;
                    const float* p = g_amsg + (size_t)agr * HD + off;
#pragma unroll
                    for (int q = 0; q < 4; q++) {
                        float4 a = *(const float4*)(p + q * 4);
                        v[q * 4 + 0] = a.x; v[q * 4 + 1] = a.y;
                        v[q * 4 + 2] = a.z; v[q * 4 + 3] = a.w;
                    }
                }
            } else {
#pragma unroll
                for (int j = 0; j < 16; j++) v[j] = 0.f;
            }
        } else {
#pragma unroll
            for (int j = 0; j < 16; j++) {
                int k = ch * BK + half * 16 + j;
                v[j] = (agr < Mrows && k < KV)
                       ? __ldg(srcA + (size_t)agr * KV + k) : 0.f;
            }
        }
    };
    auto store_A = [&](u32 bufA_hi_byteoff) {
        char* dst = smem + bufA_hi_byteoff;
        __nv_bfloat16 h[16];
#pragma unroll
        for (int j = 0; j < 16; j++) h[j] = __float2bfloat16(v[j]);
        uint4 u0, u1;
        u0.x = pkh(h[0], h[1]);   u0.y = pkh(h[2], h[3]);
        u0.z = pkh(h[4], h[5]);   u0.w = pkh(h[6], h[7]);
        u1.x = pkh(h[8], h[9]);   u1.y = pkh(h[10], h[11]);
        u1.z = pkh(h[12], h[13]); u1.w = pkh(h[14], h[15]);
        *(uint4*)(dst + arow * 80 + half * 32)      = u0;
        *(uint4*)(dst + arow * 80 + half * 32 + 16) = u1;
#pragma unroll
        for (int j = 0; j < 16; j++)
            h[j] = __float2bfloat16(v[j] - __bfloat162float(h[j]));
        u0.x = pkh(h[0], h[1]);   u0.y = pkh(h[2], h[3]);
        u0.z = pkh(h[4], h[5]);   u0.w = pkh(h[6], h[7]);
        u1.x = pkh(h[8], h[9]);   u1.y = pkh(h[10], h[11]);
        u1.z = pkh(h[12], h[13]); u1.w = pkh(h[14], h[15]);
        *(uint4*)(dst + (OFF_A_LO - OFF_A_HI) + arow * 80 + half * 32)      = u0;
        *(uint4*)(dst + (OFF_A_LO - OFF_A_HI) + arow * 80 + half * 32 + 16) = u1;
    };

    // ---- prologue: fill buffer 0 for chunk 0 ----
    issue_B(0, sbase + 0 * BUFSZ);
    load_A(0);
    store_A(0 * BUFSZ + OFF_A_HI);
    CP_WAIT0();
    __syncthreads();

#pragma unroll 1
    for (int ch = 0; ch < NCH; ch++) {
        const int b = ch & 1;
        const u32 bufC = sbase + b * BUFSZ;          // compute buffer
        const u32 bufN = sbase + (b ^ 1) * BUFSZ;    // next buffer

        // prefetch chunk ch+1 (global loads overlap MMAs below)
        if (ch + 1 < NCH) {
            issue_B(ch + 1, bufN);
            load_A(ch + 1);
        }

        // ---- compute chunk ch ----
#pragma unroll
        for (int s = 0; s < 2; s++) {
            const int kb = s * 16;
            u32 ah[4][4], al[4][4];
#pragma unroll
            for (int mi = 0; mi < 4; mi++) {
                u32 ra = (wm * 64 + mi * 16 + alrow) * 80 + (kb + alk) * 2;
                ldsm_x4(ah[mi][0], ah[mi][1], ah[mi][2], ah[mi][3],
                        bufC + OFF_A_HI + ra);
                ldsm_x4(al[mi][0], al[mi][1], al[mi][2], al[mi][3],
                        bufC + OFF_A_LO + ra);
            }
#pragma unroll
            for (int nh = 0; nh < 2; nh++) {
                const int n0 = wn * 64 + nh * 32;
                u32 bh[4][2], bl[4][2];
                u32 rb0 = (n0 + blrow) * 80 + (kb + blk) * 2;
                u32 rb1 = (n0 + 16 + blrow) * 80 + (kb + blk) * 2;
                ldsm_x4(bh[0][0], bh[0][1], bh[1][0], bh[1][1], bufC + OFF_B_HI + rb0);
                ldsm_x4(bh[2][0], bh[2][1], bh[3][0], bh[3][1], bufC + OFF_B_HI + rb1);
                ldsm_x4(bl[0][0], bl[0][1], bl[1][0], bl[1][1], bufC + OFF_B_LO + rb0);
                ldsm_x4(bl[2][0], bl[2][1], bl[3][0], bl[3][1], bufC + OFF_B_LO + rb1);
#pragma unroll
                for (int mi = 0; mi < 4; mi++)
#pragma unroll
                    for (int nt = 0; nt < 4; nt++) {
                        float* c = acc[mi][nh * 4 + nt];
                        mma_bf16(c, ah[mi], bh[nt]);   // hi*hi
                        mma_bf16(c, ah[mi], bl[nt]);   // hi*lo
                        mma_bf16(c, al[mi], bh[nt]);   // lo*hi
                    }
            }
        }

        // ---- commit prefetched A, drain cp.async, flip ----
        if (ch + 1 < NCH) {
            store_A((b ^ 1) * BUFSZ + OFF_A_HI);
            CP_WAIT0();
        }
        __syncthreads();
    }

    // ---- epilogue (fused) ----
#pragma unroll
    for (int mi = 0; mi < 4; mi++) {
        int r0 = bm + wm * 64 + mi * 16 + (lane >> 2);
#pragma unroll
        for (int nj = 0; nj < 8; nj++) {
            int cc = wn * 64 + nj * 8 + (lane & 3) * 2;
#pragma unroll
            for (int hh = 0; hh < 2; hh++) {
                int r = r0 + hh * 8;
                if (r >= Mrows) continue;
                float vx = acc[mi][nj][hh * 2 + 0];
                float vy = acc[mi][nj][hh * 2 + 1];
                size_t o = (size_t)r * HD + cc;
                if (MODE == 0) {
                    *(float2*)(g_inp + o)  = make_float2(vx, vy);
                    *(float2*)(g_msgA + o) = make_float2(fmaxf(vx, 0.f),
                                                         fmaxf(vy, 0.f));
                } else if (MODE == 1) {
                    float2 ip = *(const float2*)(g_inp + o);
                    *(float2*)(msgOut + o) = make_float2(fmaxf(ip.x + vx, 0.f),
                                                         fmaxf(ip.y + vy, 0.f));
                } else {
                    float2 bb = *(const float2*)(bo + cc);
                    *(float2*)(g_hid + o) = make_float2(fmaxf(vx + bb.x, 0.f),
                                                        fmaxf(vy + bb.y, 0.f));
                }
            }
        }
    }
}

// ============================================================================
// gather-sum: g_amsg[a] = sum_{j<6} msg[a2b[a][j]]
// ============================================================================
__global__ void __launch_bounds__(256) gather_sum_kernel(
    int src, const int* __restrict__ a2b)
{
    const float* __restrict__ msg = (src == 0) ? g_msgA : g_msgB;
    long long t = (long long)blockIdx.x * blockDim.x + threadIdx.x;
    if (t >= (long long)NA * (HD / 4)) return;
    int a = (int)(t >> 6);
    int c = (int)(t & 63);
    const int* nb = a2b + (size_t)a * MAXNB;
    float4 acc = make_float4(0.f, 0.f, 0.f, 0.f);
#pragma unroll
    for (int j = 0; j < MAXNB; j++) {
        int b = __ldg(nb + j);
        float4 v = ((const float4*)(msg + (size_t)b * HD))[c];
        acc.x += v.x; acc.y += v.y; acc.z += v.z; acc.w += v.w;
    }
    ((float4*)(g_amsg + (size_t)a * HD))[c] = acc;
}

// ============================================================================
// mol mean
// ============================================================================
__global__ void __launch_bounds__(256) mol_mean_kernel(float* __restrict__ out)
{
    int t = blockIdx.x * blockDim.x + threadIdx.x;
    if (t >= NMOL * HD) return;
    int m = t / HD, j = t % HD;
    const float* base = g_hid + (size_t)(1 + m * APM) * HD + j;
    float s = 0.f;
#pragma unroll
    for (int a = 0; a < APM; a++) s += base[(size_t)a * HD];
    out[t] = s * (1.f / APM);
}

// ============================================================================
extern "C" void kernel_launch(void* const* d_in, const int* in_sizes, int n_in,
                              void* d_out, int out_size)
{
    const float* f_atoms = (const float*)d_in[0];
    const float* f_bonds = (const float*)d_in[1];
    const int*   a2b     = (const int*)d_in[2];
    const int*   b2a     = (const int*)d_in[3];
    const int*   b2revb  = (const int*)d_in[4];
    const float* W_i     = (const float*)d_in[5];
    const float* W_h     = (const float*)d_in[6];
    const float* W_o     = (const float*)d_in[7];
    const float* b_o     = (const float*)d_in[8];
    float* out = (float*)d_out;

    cudaFuncSetAttribute(mma_gemm_kernel<0>,
                         cudaFuncAttributeMaxDynamicSharedMemorySize, SMEM_TOTAL);
    cudaFuncSetAttribute(mma_gemm_kernel<1>,
                         cudaFuncAttributeMaxDynamicSharedMemorySize, SMEM_TOTAL);
    cudaFuncSetAttribute(mma_gemm_kernel<2>,
                         cudaFuncAttributeMaxDynamicSharedMemorySize, SMEM_TOTAL);

    pack_w_kernel<<<(256 * KPAD_I + 255) / 256, 256>>>(W_i, 0);
    pack_w_kernel<<<(256 * KPAD_H + 255) / 256, 256>>>(W_h, 1);
    pack_w_kernel<<<(256 * KPAD_O + 255) / 256, 256>>>(W_o, 2);

    const int GB = (NB + BMT - 1) / BMT;   // 2032
    const int GA = (NA + BMT - 1) / BMT;   // 938

    long long gsT = (long long)NA * (HD / 4);
    int gsBlocks  = (int)((gsT + 255) / 256);
    int mmBlocks  = (NMOL * HD + 255) / 256;

    mma_gemm_kernel<0><<<GB, 256, SMEM_TOTAL>>>(f_bonds, b2a, b2revb, b_o, 0);
    gather_sum_kernel<<<gsBlocks, 256>>>(0, a2b);
    mma_gemm_kernel<1><<<GB, 256, SMEM_TOTAL>>>(nullptr, b2a, b2revb, b_o, 0);
    gather_sum_kernel<<<gsBlocks, 256>>>(1, a2b);
    mma_gemm_kernel<1><<<GB, 256, SMEM_TOTAL>>>(nullptr, b2a, b2revb, b_o, 1);
    gather_sum_kernel<<<gsBlocks, 256>>>(0, a2b);
    mma_gemm_kernel<2><<<GA, 256, SMEM_TOTAL>>>(f_atoms, b2a, b2revb, b_o, 0);
    mol_mean_kernel<<<mmBlocks, 256>>>(out);
}

// round 6
// speedup vs baseline: 1.1695x; 1.1695x over previous
#include <cuda_runtime.h>
#include <cuda_bf16.h>
#include <cstdint>
#include <cstddef>

#define NA 120001
#define NB 260001
#define AF 133
#define BF 147
#define HD 256
#define MAXNB 6
#define NMOL 6000
#define APM 20

#define BMT 128           // M rows per CTA
#define BNT 128           // N cols per CTA (2 CTAs in N via blockIdx.y)
#define BK  32            // K elements per chunk

#define KPAD_I 160
#define KPAD_H 256
#define KPAD_O 416

// SMEM per buffer (stride 80 B per 32-element bf16 row):
//   A_HI 128*80=10240, A_LO 10240, B_HI 128*80=10240, B_LO 10240 => 40960
#define OFF_A_HI 0
#define OFF_A_LO 10240
#define OFF_B_HI 20480
#define OFF_B_LO 30720
#define BUFSZ    40960
#define SMEM_TOTAL (2 * BUFSZ)   // 81920 -> 2 CTAs/SM

typedef unsigned int u32;

// ---------------- scratch (device globals; no allocation allowed) ----------
__device__ float g_inp [(size_t)NB * HD];
__device__ float g_msgA[(size_t)NB * HD];
__device__ float g_msgB[(size_t)NB * HD];
__device__ float g_amsg[(size_t)NA * HD];
__device__ float g_hid [(size_t)NA * HD];

// prepacked transposed weights, bf16 hi/lo: [term][N=256][Kpad]
__device__ __nv_bfloat16 g_Bi[2][256 * KPAD_I];
__device__ __nv_bfloat16 g_Bh[2][256 * KPAD_H];
__device__ __nv_bfloat16 g_Bo[2][256 * KPAD_O];

// ---------------- helpers ---------------------------------------------------
__device__ __forceinline__ u32 smem_to_u32(const void* p) {
    u32 a;
    asm("{ .reg .u64 t; cvta.to.shared.u64 t, %1; cvt.u32.u64 %0, t; }"
        : "=r"(a) : "l"(p));
    return a;
}
__device__ __forceinline__ void ldsm_x4(u32& r0, u32& r1, u32& r2, u32& r3, u32 a) {
    asm volatile("ldmatrix.sync.aligned.m8n8.x4.shared.b16 {%0,%1,%2,%3}, [%4];"
                 : "=r"(r0), "=r"(r1), "=r"(r2), "=r"(r3) : "r"(a));
}
__device__ __forceinline__ void mma_bf16(float* c, const u32* a, const u32* b) {
    asm volatile(
        "mma.sync.aligned.m16n8k16.row.col.f32.bf16.bf16.f32 "
        "{%0,%1,%2,%3},{%4,%5,%6,%7},{%8,%9},{%0,%1,%2,%3};"
        : "+f"(c[0]), "+f"(c[1]), "+f"(c[2]), "+f"(c[3])
        : "r"(a[0]), "r"(a[1]), "r"(a[2]), "r"(a[3]), "r"(b[0]), "r"(b[1]));
}
__device__ __forceinline__ u32 pkh(__nv_bfloat16 a, __nv_bfloat16 b) {
    return (u32)__bfloat16_as_ushort(a) | ((u32)__bfloat16_as_ushort(b) << 16);
}
__device__ __forceinline__ void cp16(u32 dst, const void* src) {
    asm volatile("cp.async.cg.shared.global [%0], [%1], 16;"
                 :: "r"(dst), "l"(src));
}
#define CP_COMMIT() asm volatile("cp.async.commit_group;" ::: "memory")
#define CP_WAIT0()  asm volatile("cp.async.wait_group 0;"  ::: "memory")

// ---------------- weight prepack: transpose + hi/lo split + zero pad -------
__global__ void pack_w_kernel(const float* __restrict__ W, int sel)
{
    int KPAD = (sel == 0) ? KPAD_I : (sel == 1) ? KPAD_H : KPAD_O;
    __nv_bfloat16* imgHi = (sel == 0) ? g_Bi[0] : (sel == 1) ? g_Bh[0] : g_Bo[0];
    __nv_bfloat16* imgLo = (sel == 0) ? g_Bi[1] : (sel == 1) ? g_Bh[1] : g_Bo[1];
    int t = blockIdx.x * blockDim.x + threadIdx.x;
    if (t >= 256 * KPAD) return;
    int n = t / KPAD, kk = t % KPAD;
    int srck;
    if (sel == 0)      srck = (kk < BF) ? kk : -1;
    else if (sel == 1) srck = kk;
    else               srck = (kk < 160) ? (kk < AF ? kk : -1) : (AF + (kk - 160));
    float w = (srck >= 0) ? W[(size_t)srck * HD + n] : 0.f;
    __nv_bfloat16 hi = __float2bfloat16(w);
    __nv_bfloat16 lo = __float2bfloat16(w - __bfloat162float(hi));
    imgHi[(size_t)n * KPAD + kk] = hi;
    imgLo[(size_t)n * KPAD + kk] = lo;
}

// ---------------- unified mma.sync GEMM, 128x128 CTA, 2 CTAs/SM ------------
// MODE 0: g_inp = f_bonds @ W_i ; g_msgA = relu(g_inp)
// MODE 1: msgOut = relu(g_inp + (g_amsg[b2a] - msgIn[b2revb]) @ W_h)
// MODE 2: g_hid = relu([f_atoms | g_amsg] @ W_o + b_o)
template <int MODE>
__global__ void __launch_bounds__(256, 2) mma_gemm_kernel(
    const float* __restrict__ srcA,
    const int* __restrict__ b2a, const int* __restrict__ b2revb,
    const float* __restrict__ bo, int srcSel)
{
    constexpr int NCH   = (MODE == 0) ? 5 : (MODE == 1) ? 8 : 13;
    constexpr int KPAD  = (MODE == 0) ? KPAD_I : (MODE == 1) ? KPAD_H : KPAD_O;
    constexpr int Mrows = (MODE == 2) ? NA : NB;
    constexpr int KV    = (MODE == 0) ? BF : AF;

    const float* __restrict__ msgIn  = (srcSel == 0) ? g_msgA : g_msgB;
    float*       __restrict__ msgOut = (srcSel == 0) ? g_msgB : g_msgA;
    const __nv_bfloat16* imgHi =
        (MODE == 0) ? g_Bi[0] : (MODE == 1) ? g_Bh[0] : g_Bo[0];
    const __nv_bfloat16* imgLo =
        (MODE == 0) ? g_Bi[1] : (MODE == 1) ? g_Bh[1] : g_Bo[1];

    extern __shared__ char smem[];
    const u32 sbase = smem_to_u32(smem);

    const int tid  = threadIdx.x;
    const int lane = tid & 31;
    const int wid  = tid >> 5;
    const int wm   = wid >> 1;        // 0..3  (M: 32 rows each)
    const int wn   = wid & 1;         // 0..1  (N: 64 cols each)
    const int bm   = blockIdx.x * BMT;
    const int bn   = blockIdx.y * BNT; // N half

    // A-loader coords: 2 threads per row, 16 cols each
    const int arow = tid >> 1;        // 0..127
    const int half = tid & 1;         // col group: half*16
    const int agr  = bm + arow;
    const float* p1 = nullptr;
    const float* p2 = nullptr;
    if (MODE == 1 && agr < NB) {
        p1 = g_amsg + (size_t)__ldg(b2a + agr)    * HD;
        p2 = msgIn  + (size_t)__ldg(b2revb + agr) * HD;
    }

    // ldmatrix lane addressing
    const int alrow = lane & 15;
    const int alk   = (lane & 16) ? 8 : 0;
    const int blrow = (lane & 7) + ((lane & 16) ? 8 : 0);
    const int blk   = (lane & 8)  ? 8 : 0;

    float acc[2][8][4];
#pragma unroll
    for (int i = 0; i < 2; i++)
#pragma unroll
        for (int j = 0; j < 8; j++)
#pragma unroll
            for (int q = 0; q < 4; q++) acc[i][j][q] = 0.f;

    float v[16];

    auto issue_B = [&](int ch, u32 bufB) {
#pragma unroll
        for (int i = 0; i < 2; i++) {
            int idx = tid + 256 * i;
            int n = idx >> 2, seg = idx & 3;     // n: 0..127 local
            cp16(bufB + OFF_B_HI + n * 80 + seg * 16,
                 imgHi + (size_t)(bn + n) * KPAD + ch * BK + seg * 8);
            cp16(bufB + OFF_B_LO + n * 80 + seg * 16,
                 imgLo + (size_t)(bn + n) * KPAD + ch * BK + seg * 8);
        }
        CP_COMMIT();
    };
    auto load_A = [&](int ch) {
        const bool vec = (MODE == 1) || (MODE == 2 && ch >= 5);
        if (vec) {
            if (agr < Mrows) {
                if (MODE == 1) {
                    int off = ch * BK + half * 16;
#pragma unroll
                    for (int q = 0; q < 4; q++) {
                        float4 a = *(const float4*)(p1 + off + q * 4);
                        float4 b = *(const float4*)(p2 + off + q * 4);
                        v[q * 4 + 0] = a.x - b.x; v[q * 4 + 1] = a.y - b.y;
                        v[q * 4 + 2] = a.z - b.z; v[q * 4 + 3] = a.w - b.w;
                    }
                } else {
                    int off = (ch - 5) * BK + half * 16;
                    const float* p = g_amsg + (size_t)agr * HD + off;
#pragma unroll
                    for (int q = 0; q < 4; q++) {
                        float4 a = *(const float4*)(p + q * 4);
                        v[q * 4 + 0] = a.x; v[q * 4 + 1] = a.y;
                        v[q * 4 + 2] = a.z; v[q * 4 + 3] = a.w;
                    }
                }
            } else {
#pragma unroll
                for (int j = 0; j < 16; j++) v[j] = 0.f;
            }
        } else {
#pragma unroll
            for (int j = 0; j < 16; j++) {
                int k = ch * BK + half * 16 + j;
                v[j] = (agr < Mrows && k < KV)
                       ? __ldg(srcA + (size_t)agr * KV + k) : 0.f;
            }
        }
    };
    auto store_A = [&](u32 bufA_hi_byteoff) {
        char* dst = smem + bufA_hi_byteoff;
        __nv_bfloat16 h[16];
#pragma unroll
        for (int j = 0; j < 16; j++) h[j] = __float2bfloat16(v[j]);
        uint4 u0, u1;
        u0.x = pkh(h[0], h[1]);   u0.y = pkh(h[2], h[3]);
        u0.z = pkh(h[4], h[5]);   u0.w = pkh(h[6], h[7]);
        u1.x = pkh(h[8], h[9]);   u1.y = pkh(h[10], h[11]);
        u1.z = pkh(h[12], h[13]); u1.w = pkh(h[14], h[15]);
        *(uint4*)(dst + arow * 80 + half * 32)      = u0;
        *(uint4*)(dst + arow * 80 + half * 32 + 16) = u1;
#pragma unroll
        for (int j = 0; j < 16; j++)
            h[j] = __float2bfloat16(v[j] - __bfloat162float(h[j]));
        u0.x = pkh(h[0], h[1]);   u0.y = pkh(h[2], h[3]);
        u0.z = pkh(h[4], h[5]);   u0.w = pkh(h[6], h[7]);
        u1.x = pkh(h[8], h[9]);   u1.y = pkh(h[10], h[11]);
        u1.z = pkh(h[12], h[13]); u1.w = pkh(h[14], h[15]);
        *(uint4*)(dst + (OFF_A_LO - OFF_A_HI) + arow * 80 + half * 32)      = u0;
        *(uint4*)(dst + (OFF_A_LO - OFF_A_HI) + arow * 80 + half * 32 + 16) = u1;
    };

    // ---- prologue: fill buffer 0 for chunk 0 ----
    issue_B(0, sbase + 0 * BUFSZ);
    load_A(0);
    store_A(0 * BUFSZ + OFF_A_HI);
    CP_WAIT0();
    __syncthreads();

#pragma unroll 1
    for (int ch = 0; ch < NCH; ch++) {
        const int b = ch & 1;
        const u32 bufC = sbase + b * BUFSZ;
        const u32 bufN = sbase + (b ^ 1) * BUFSZ;

        if (ch + 1 < NCH) {
            issue_B(ch + 1, bufN);
            load_A(ch + 1);
        }

        // ---- compute chunk ch ----
#pragma unroll
        for (int s = 0; s < 2; s++) {
            const int kb = s * 16;
            u32 ah[2][4], al[2][4];
#pragma unroll
            for (int mi = 0; mi < 2; mi++) {
                u32 ra = (wm * 32 + mi * 16 + alrow) * 80 + (kb + alk) * 2;
                ldsm_x4(ah[mi][0], ah[mi][1], ah[mi][2], ah[mi][3],
                        bufC + OFF_A_HI + ra);
                ldsm_x4(al[mi][0], al[mi][1], al[mi][2], al[mi][3],
                        bufC + OFF_A_LO + ra);
            }
#pragma unroll
            for (int nh = 0; nh < 2; nh++) {
                const int n0 = wn * 64 + nh * 32;
                u32 bh[4][2], bl[4][2];
                u32 rb0 = (n0 + blrow) * 80 + (kb + blk) * 2;
                u32 rb1 = (n0 + 16 + blrow) * 80 + (kb + blk) * 2;
                ldsm_x4(bh[0][0], bh[0][1], bh[1][0], bh[1][1], bufC + OFF_B_HI + rb0);
                ldsm_x4(bh[2][0], bh[2][1], bh[3][0], bh[3][1], bufC + OFF_B_HI + rb1);
                ldsm_x4(bl[0][0], bl[0][1], bl[1][0], bl[1][1], bufC + OFF_B_LO + rb0);
                ldsm_x4(bl[2][0], bl[2][1], bl[3][0], bl[3][1], bufC + OFF_B_LO + rb1);
#pragma unroll
                for (int mi = 0; mi < 2; mi++)
#pragma unroll
                    for (int nt = 0; nt < 4; nt++) {
                        float* c = acc[mi][nh * 4 + nt];
                        mma_bf16(c, ah[mi], bh[nt]);   // hi*hi
                        mma_bf16(c, ah[mi], bl[nt]);   // hi*lo
                        mma_bf16(c, al[mi], bh[nt]);   // lo*hi
                    }
            }
        }

        if (ch + 1 < NCH) {
            store_A((b ^ 1) * BUFSZ + OFF_A_HI);
            CP_WAIT0();
        }
        __syncthreads();
    }

    // ---- epilogue (fused) ----
#pragma unroll
    for (int mi = 0; mi < 2; mi++) {
        int r0 = bm + wm * 32 + mi * 16 + (lane >> 2);
#pragma unroll
        for (int nj = 0; nj < 8; nj++) {
            int cc = bn + wn * 64 + nj * 8 + (lane & 3) * 2;
#pragma unroll
            for (int hh = 0; hh < 2; hh++) {
                int r = r0 + hh * 8;
                if (r >= Mrows) continue;
                float vx = acc[mi][nj][hh * 2 + 0];
                float vy = acc[mi][nj][hh * 2 + 1];
                size_t o = (size_t)r * HD + cc;
                if (MODE == 0) {
                    *(float2*)(g_inp + o)  = make_float2(vx, vy);
                    *(float2*)(g_msgA + o) = make_float2(fmaxf(vx, 0.f),
                                                         fmaxf(vy, 0.f));
                } else if (MODE == 1) {
                    float2 ip = *(const float2*)(g_inp + o);
                    *(float2*)(msgOut + o) = make_float2(fmaxf(ip.x + vx, 0.f),
                                                         fmaxf(ip.y + vy, 0.f));
                } else {
                    float2 bb = *(const float2*)(bo + cc);
                    *(float2*)(g_hid + o) = make_float2(fmaxf(vx + bb.x, 0.f),
                                                        fmaxf(vy + bb.y, 0.f));
                }
            }
        }
    }
}

// ============================================================================
// gather-sum: g_amsg[a] = sum_{j<6} msg[a2b[a][j]]
// ============================================================================
__global__ void __launch_bounds__(256) gather_sum_kernel(
    int src, const int* __restrict__ a2b)
{
    const float* __restrict__ msg = (src == 0) ? g_msgA : g_msgB;
    long long t = (long long)blockIdx.x * blockDim.x + threadIdx.x;
    if (t >= (long long)NA * (HD / 4)) return;
    int a = (int)(t >> 6);
    int c = (int)(t & 63);
    const int* nb = a2b + (size_t)a * MAXNB;
    float4 acc = make_float4(0.f, 0.f, 0.f, 0.f);
#pragma unroll
    for (int j = 0; j < MAXNB; j++) {
        int b = __ldg(nb + j);
        float4 v = ((const float4*)(msg + (size_t)b * HD))[c];
        acc.x += v.x; acc.y += v.y; acc.z += v.z; acc.w += v.w;
    }
    ((float4*)(g_amsg + (size_t)a * HD))[c] = acc;
}

// ============================================================================
// mol mean
// ============================================================================
__global__ void __launch_bounds__(256) mol_mean_kernel(float* __restrict__ out)
{
    int t = blockIdx.x * blockDim.x + threadIdx.x;
    if (t >= NMOL * HD) return;
    int m = t / HD, j = t % HD;
    const float* base = g_hid + (size_t)(1 + m * APM) * HD + j;
    float s = 0.f;
#pragma unroll
    for (int a = 0; a < APM; a++) s += base[(size_t)a * HD];
    out[t] = s * (1.f / APM);
}

// ============================================================================
extern "C" void kernel_launch(void* const* d_in, const int* in_sizes, int n_in,
                              void* d_out, int out_size)
{
    const float* f_atoms = (const float*)d_in[0];
    const float* f_bonds = (const float*)d_in[1];
    const int*   a2b     = (const int*)d_in[2];
    const int*   b2a     = (const int*)d_in[3];
    const int*   b2revb  = (const int*)d_in[4];
    const float* W_i     = (const float*)d_in[5];
    const float* W_h     = (const float*)d_in[6];
    const float* W_o     = (const float*)d_in[7];
    const float* b_o     = (const float*)d_in[8];
    float* out = (float*)d_out;

    cudaFuncSetAttribute(mma_gemm_kernel<0>,
                         cudaFuncAttributeMaxDynamicSharedMemorySize, SMEM_TOTAL);
    cudaFuncSetAttribute(mma_gemm_kernel<1>,
                         cudaFuncAttributeMaxDynamicSharedMemorySize, SMEM_TOTAL);
    cudaFuncSetAttribute(mma_gemm_kernel<2>,
                         cudaFuncAttributeMaxDynamicSharedMemorySize, SMEM_TOTAL);

    pack_w_kernel<<<(256 * KPAD_I + 255) / 256, 256>>>(W_i, 0);
    pack_w_kernel<<<(256 * KPAD_H + 255) / 256, 256>>>(W_h, 1);
    pack_w_kernel<<<(256 * KPAD_O + 255) / 256, 256>>>(W_o, 2);

    const dim3 GB((NB + BMT - 1) / BMT, 2);   // 2032 x 2
    const dim3 GA((NA + BMT - 1) / BMT, 2);   // 938 x 2

    long long gsT = (long long)NA * (HD / 4);
    int gsBlocks  = (int)((gsT + 255) / 256);
    int mmBlocks  = (NMOL * HD + 255) / 256;

    mma_gemm_kernel<0><<<GB, 256, SMEM_TOTAL>>>(f_bonds, b2a, b2revb, b_o, 0);
    gather_sum_kernel<<<gsBlocks, 256>>>(0, a2b);
    mma_gemm_kernel<1><<<GB, 256, SMEM_TOTAL>>>(nullptr, b2a, b2revb, b_o, 0);
    gather_sum_kernel<<<gsBlocks, 256>>>(1, a2b);
    mma_gemm_kernel<1><<<GB, 256, SMEM_TOTAL>>>(nullptr, b2a, b2revb, b_o, 1);
    gather_sum_kernel<<<gsBlocks, 256>>>(0, a2b);
    mma_gemm_kernel<2><<<GA, 256, SMEM_TOTAL>>>(f_atoms, b2a, b2revb, b_o, 0);
    mol_mean_kernel<<<mmBlocks, 256>>>(out);
}